// round 12
// baseline (speedup 1.0000x reference)
#include <cuda_runtime.h>
#include <math.h>
#include <stdint.h>

#define BATCH 2
#define CH    64
#define CK    8
#define NPIX  9216   // 96*96
#define NB    256    // depth bins
#define BPB   16     // bins per producer CTA
#define NPROD 32     // producer CTAs total (16 per batch)
#define NCTA  144    // total CTAs (72 x 2)
#define DLO   (-6.0f)
#define DSCALE ((float)NB / 12.0f)
#define LOG2E 1.4426950408889634f

// Global scratch (allocation-free rule). Counters reset by last exiting CTA.
__device__ float g_l2c[BATCH * NB];
__device__ float g_k_hi[BATCH * NB * CK];
__device__ float g_k_lo[BATCH * NB * CK];
__device__ float g_v[BATCH * CH * NB];
__device__ int   g_bar  = 0;
__device__ int   g_exit = 0;

__device__ __forceinline__ float to_tf32(float x) {
    float r; asm("cvt.rna.tf32.f32 %0, %1;" : "=f"(r) : "f"(x)); return r;
}
__device__ __forceinline__ float ex2f(float x) {
    float r; asm("ex2.approx.f32 %0, %1;" : "=f"(r) : "f"(x)); return r;
}
__device__ __forceinline__ void mma4(float* d, const float* a, float b0, float b1) {
    asm("mma.sync.aligned.m16n8k8.row.col.f32.tf32.tf32.f32 "
        "{%0,%1,%2,%3},{%4,%5,%6,%7},{%8,%9},{%0,%1,%2,%3};"
        : "+f"(d[0]), "+f"(d[1]), "+f"(d[2]), "+f"(d[3])
        : "r"(__float_as_uint(a[0])), "r"(__float_as_uint(a[1])),
          "r"(__float_as_uint(a[2])), "r"(__float_as_uint(a[3])),
          "r"(__float_as_uint(b0)), "r"(__float_as_uint(b1)));
}

// ---------------- smem layout (float indices) ----------------
#define SL    0            // 128 rowsums
#define SQ    128          // q[128][8]
#define SL2C  1152         // 256
// producer-only scratch, dead after barrier (overlaps SKH/SKL/SV zone):
#define BK_CNT  1408       // 256 ints
#define BK_SUM  1664
#define BK_MEAN 1920
#define BK_WA   1936
#define BK_BA   2000
#define BK_BD   2064
#define BK_BC   2128
#define BK_WC   2144       // 512
#define BK_WD   2656       // 4096
#define BK_DF   6752       // 64 x 16
// post-barrier:
#define KPAD  12
#define VPAD  264
#define SKH   1408         // 256 x 12
#define SKL   4480
#define SV    7552         // 64 x 264
#define SWB   24448        // 512
#define SBB   24960        // 8
#define FMT   24968        // 64 x 128
// epilogue (overlaps everything from 1408 up):
#define REDB  1408
#define RPAD  68
#define RSZ   (128 * RPAD)
#define SMEM_FLOATS (REDB + 4 * RSZ)   // 36224 floats = 144896 B

__global__ void __launch_bounds__(512, 1) attn_kernel(
        const float* __restrict__ fm,   const float* __restrict__ depth,
        const float* __restrict__ wa,   const float* __restrict__ ba,
        const float* __restrict__ wb,   const float* __restrict__ bb,
        const float* __restrict__ wc,   const float* __restrict__ bc,
        const float* __restrict__ wd,   const float* __restrict__ bd,
        float* __restrict__ out) {
    extern __shared__ float sm[];

    const int t    = threadIdx.x;
    const int lane = t & 31;
    const int gid  = lane >> 2;
    const int tig  = lane & 3;
    const int wid  = t >> 5;
    const int qi   = wid & 3;
    const int kh   = wid >> 2;
    const int b    = blockIdx.y;
    const int n0   = blockIdx.x * 128;
    const bool producer = (blockIdx.x < NB / BPB);   // 16 per batch

    // =================== pre-barrier phase ===================
    if (producer) {
        // ---- binkv: histogram (per-warp privatized) + k/v projection ----
        int* bcnt = (int*)&sm[BK_CNT];
        const int w = t >> 5;
        const int bin0 = blockIdx.x * BPB;

        if (t < 256) { bcnt[t] = 0; sm[BK_SUM + t] = 0.0f; }
        if (t < CH) { sm[BK_WA + t] = wa[t]; sm[BK_BA + t] = ba[t]; sm[BK_BD + t] = bd[t]; }
        if (t < CK) sm[BK_BC + t] = bc[t];
        if (t < CK * CH) sm[BK_WC + t] = wc[t];
        for (int i = t; i < CH * CH; i += 512) sm[BK_WD + i] = wd[i];
        __syncthreads();

        const float* dep = depth + (size_t)b * NPIX;
#pragma unroll
        for (int i = 0; i < NPIX / 512; i++) {
            const float v = dep[t + i * 512];
            int bi = (int)((v - DLO) * DSCALE);
            bi = min(max(bi, 0), NB - 1);
            const int local = bi - bin0;
            if ((unsigned)local < BPB) {
                atomicAdd(&bcnt[w * BPB + local], 1);
                atomicAdd(&sm[BK_SUM + w * BPB + local], v);
            }
        }
        __syncthreads();

        if (t < BPB) {
            int   c = 0;
            float s = 0.0f;
#pragma unroll
            for (int ww = 0; ww < 16; ww++) { c += bcnt[ww * BPB + t]; s += sm[BK_SUM + ww * BPB + t]; }
            sm[BK_MEAN + t] = (c > 0) ? (s / (float)c) : 0.0f;
            g_l2c[b * NB + bin0 + t] = (c > 0) ? log2f((float)c) : -100000.0f;
        }
        __syncthreads();

        const int bin = t & (BPB - 1);
        const int g   = t >> 4;
        const float d = sm[BK_MEAN + bin];
#pragma unroll
        for (int cc = 0; cc < 2; cc++) {
            const int c = g * 2 + cc;
            sm[BK_DF + c * BPB + bin] = fmaxf(fmaf(sm[BK_WA + c], d, sm[BK_BA + c]), 0.0f);
        }
        __syncthreads();

        if (g < 8) {
            float acc = sm[BK_BC + g];
#pragma unroll 8
            for (int c = 0; c < CH; c++)
                acc = fmaf(sm[BK_WC + g * CH + c], sm[BK_DF + c * BPB + bin], acc);
            const float ks = acc * LOG2E;
            const float hi = to_tf32(ks);
            g_k_hi[((size_t)b * NB + bin0 + bin) * CK + g] = hi;
            g_k_lo[((size_t)b * NB + bin0 + bin) * CK + g] = to_tf32(ks - hi);
        }
        {
            float a0 = sm[BK_BD + g * 2], a1 = sm[BK_BD + g * 2 + 1];
#pragma unroll 8
            for (int c = 0; c < CH; c++) {
                const float f = sm[BK_DF + c * BPB + bin];
                a0 = fmaf(sm[BK_WD + (g * 2) * CH + c], f, a0);
                a1 = fmaf(sm[BK_WD + (g * 2 + 1) * CH + c], f, a1);
            }
            float* vo = g_v + (size_t)b * CH * NB + bin0 + bin;
            vo[(size_t)(g * 2) * NB]     = to_tf32(a0);
            vo[(size_t)(g * 2 + 1) * NB] = to_tf32(a1);
        }
        __syncthreads();
        if (t == 0) { __threadfence(); atomicAdd(&g_bar, 1); }
    } else {
        // ---- overlap: fm tile + qproj while producers run ----
        if (t < 128) sm[SL + t] = 0.0f;
        sm[SWB + t] = wb[t];
        if (t < 8) sm[SBB + t] = bb[t];
        {
            const float* fmb = fm + (size_t)b * CH * NPIX + n0;
#pragma unroll
            for (int i = 0; i < 4; i++) {
                const int idx = t + i * 512;
                const int c   = idx >> 5;
                const int r4  = (idx & 31) * 4;
                *(float4*)&sm[FMT + c * 128 + r4] = *(const float4*)&fmb[(size_t)c * NPIX + r4];
            }
        }
        __syncthreads();
        {
            const int r  = t & 127;
            const int jp = t >> 7;
            float a0 = sm[SBB + 2 * jp], a1 = sm[SBB + 2 * jp + 1];
#pragma unroll 8
            for (int c = 0; c < CH; c++) {
                const float fv = sm[FMT + c * 128 + r];
                a0 = fmaf(sm[SWB + (2 * jp) * CH + c], fv, a0);
                a1 = fmaf(sm[SWB + (2 * jp + 1) * CH + c], fv, a1);
            }
            sm[SQ + r * 8 + 2 * jp]     = a0;
            sm[SQ + r * 8 + 2 * jp + 1] = a1;
        }
    }

    // =================== grid barrier ===================
    if (t == 0) {
        volatile int* vb = &g_bar;
        while (*vb < NPROD) __nanosleep(64);
        __threadfence();
    }
    __syncthreads();

    // producers catch up on their own prologue after the barrier
    if (producer) {
        if (t < 128) sm[SL + t] = 0.0f;
        sm[SWB + t] = wb[t];
        if (t < 8) sm[SBB + t] = bb[t];
        {
            const float* fmb = fm + (size_t)b * CH * NPIX + n0;
#pragma unroll
            for (int i = 0; i < 4; i++) {
                const int idx = t + i * 512;
                const int c   = idx >> 5;
                const int r4  = (idx & 31) * 4;
                *(float4*)&sm[FMT + c * 128 + r4] = *(const float4*)&fmb[(size_t)c * NPIX + r4];
            }
        }
        __syncthreads();
        {
            const int r  = t & 127;
            const int jp = t >> 7;
            float a0 = sm[SBB + 2 * jp], a1 = sm[SBB + 2 * jp + 1];
#pragma unroll 8
            for (int c = 0; c < CH; c++) {
                const float fv = sm[FMT + c * 128 + r];
                a0 = fmaf(sm[SWB + (2 * jp) * CH + c], fv, a0);
                a1 = fmaf(sm[SWB + (2 * jp + 1) * CH + c], fv, a1);
            }
            sm[SQ + r * 8 + 2 * jp]     = a0;
            sm[SQ + r * 8 + 2 * jp + 1] = a1;
        }
    }

    // ---- load K/V/l2c into smem (all CTAs) ----
    if (t < NB) sm[SL2C + t] = g_l2c[b * NB + t];
    {
        const float4 k4h = ((const float4*)(g_k_hi + (size_t)b * NB * CK))[t];
        const float4 k4l = ((const float4*)(g_k_lo + (size_t)b * NB * CK))[t];
        const int off = (t >> 1) * KPAD + (t & 1) * 4;
        *(float4*)&sm[SKH + off] = k4h;
        *(float4*)&sm[SKL + off] = k4l;
    }
    {
        const float4* vg4 = (const float4*)(g_v + (size_t)b * CH * NB);
#pragma unroll
        for (int j = 0; j < 8; j++) {
            const int i  = t + j * 512;
            const int c  = i >> 6;
            const int b4 = (i & 63) * 4;
            *(float4*)&sm[SV + c * VPAD + b4] = vg4[i];
        }
    }
    __syncthreads();

    // ---- Q A-fragments (hi/lo) ----
    float qhi[2][4], qlo[2][4];
#pragma unroll
    for (int sub = 0; sub < 2; sub++) {
        const int qbase = qi * 32 + sub * 16;
        float v0 = sm[SQ + (qbase + gid) * 8 + tig];
        float v1 = sm[SQ + (qbase + gid + 8) * 8 + tig];
        float v2 = sm[SQ + (qbase + gid) * 8 + tig + 4];
        float v3 = sm[SQ + (qbase + gid + 8) * 8 + tig + 4];
        qhi[sub][0] = to_tf32(v0); qlo[sub][0] = to_tf32(v0 - qhi[sub][0]);
        qhi[sub][1] = to_tf32(v1); qlo[sub][1] = to_tf32(v1 - qhi[sub][1]);
        qhi[sub][2] = to_tf32(v2); qlo[sub][2] = to_tf32(v2 - qhi[sub][2]);
        qhi[sub][3] = to_tf32(v3); qlo[sub][3] = to_tf32(v3 - qhi[sub][3]);
    }

    float acc[2][8][4] = {};
    float lpart[2][2]  = {};

    // ---- mainloop: sync-free (unchanged from R11) ----
#pragma unroll
    for (int mt = 0; mt < NB / 64; mt++) {
#pragma unroll
        for (int mc = 0; mc < 2; mc++) {
            const int row = mt * 64 + kh * 16 + mc * 8;
            const float* krh = &sm[SKH + (row + gid) * KPAD];
            const float* krl = &sm[SKL + (row + gid) * KPAD];
            const float b0h = krh[tig], b1h = krh[tig + 4];
            const float b0l = krl[tig], b1l = krl[tig + 4];
            const float2 lc = *(const float2*)&sm[SL2C + row + 2 * tig];

            float p[2][4];
#pragma unroll
            for (int sub = 0; sub < 2; sub++) {
                float d[4] = {lc.x, lc.y, lc.x, lc.y};
                mma4(d, qhi[sub], b0h, b1h);
                mma4(d, qhi[sub], b0l, b1l);
                mma4(d, qlo[sub], b0h, b1h);
                p[sub][0] = to_tf32(ex2f(d[0]));
                p[sub][1] = to_tf32(ex2f(d[1]));
                p[sub][2] = to_tf32(ex2f(d[2]));
                p[sub][3] = to_tf32(ex2f(d[3]));
                lpart[sub][0] += p[sub][0] + p[sub][1];
                lpart[sub][1] += p[sub][2] + p[sub][3];
            }
            const float a0[4] = {p[0][0], p[0][2], p[0][1], p[0][3]};
            const float a1[4] = {p[1][0], p[1][2], p[1][1], p[1][3]};
#pragma unroll
            for (int nc = 0; nc < 8; nc++) {
                const float2 bv = *(const float2*)&sm[SV + (nc * 8 + gid) * VPAD + row + 2 * tig];
                mma4(acc[0][nc], a0, bv.x, bv.y);
                mma4(acc[1][nc], a1, bv.x, bv.y);
            }
        }
    }

    // ---- row-sum reduction ----
#pragma unroll
    for (int sub = 0; sub < 2; sub++)
#pragma unroll
        for (int h = 0; h < 2; h++) {
            float v = lpart[sub][h];
            v += __shfl_xor_sync(0xffffffff, v, 1);
            v += __shfl_xor_sync(0xffffffff, v, 2);
            if (tig == 0) atomicAdd(&sm[SL + qi * 32 + sub * 16 + gid + h * 8], v);
        }
    __syncthreads();

    // ---- one-round partial dump ----
    {
        float* reg = sm + REDB + kh * RSZ;
#pragma unroll
        for (int sub = 0; sub < 2; sub++) {
            const int qrow = qi * 32 + sub * 16 + gid;
#pragma unroll
            for (int nc = 0; nc < 8; nc++) {
                const int c = nc * 8 + 2 * tig;
                *(float2*)&reg[qrow * RPAD + c]       = make_float2(acc[sub][nc][0], acc[sub][nc][1]);
                *(float2*)&reg[(qrow + 8) * RPAD + c] = make_float2(acc[sub][nc][2], acc[sub][nc][3]);
            }
        }
    }
    __syncthreads();

    // ---- sum 4 partials, scale, coalesced store ----
    {
        const int q  = t & 127;
        const int cq = t >> 7;
        const float rl = 1.0f / sm[SL + q];
        const int base = q * RPAD + cq * 16;
        float* ob = out + ((size_t)b * CH + cq * 16) * NPIX + n0 + q;
#pragma unroll
        for (int j = 0; j < 4; j++) {
            float4 s0 = *(float4*)&sm[REDB + 0 * RSZ + base + j * 4];
            float4 s1 = *(float4*)&sm[REDB + 1 * RSZ + base + j * 4];
            float4 s2 = *(float4*)&sm[REDB + 2 * RSZ + base + j * 4];
            float4 s3 = *(float4*)&sm[REDB + 3 * RSZ + base + j * 4];
            ob[(size_t)(j * 4 + 0) * NPIX] = (s0.x + s1.x + s2.x + s3.x) * rl;
            ob[(size_t)(j * 4 + 1) * NPIX] = (s0.y + s1.y + s2.y + s3.y) * rl;
            ob[(size_t)(j * 4 + 2) * NPIX] = (s0.z + s1.z + s2.z + s3.z) * rl;
            ob[(size_t)(j * 4 + 3) * NPIX] = (s0.w + s1.w + s2.w + s3.w) * rl;
        }
    }

    // ---- replay-safe counter reset: last exiting CTA zeroes both ----
    if (t == 0) {
        const int e = atomicAdd(&g_exit, 1);
        if (e == NCTA - 1) { g_bar = 0; g_exit = 0; __threadfence(); }
    }
}

// ---------------------------------------------------------------------------
extern "C" void kernel_launch(void* const* d_in, const int* in_sizes, int n_in,
                              void* d_out, int out_size) {
    const float* fm    = (const float*)d_in[0];
    const float* depth = (const float*)d_in[1];
    const float* wa    = (const float*)d_in[2];
    const float* ba    = (const float*)d_in[3];
    const float* wb    = (const float*)d_in[4];
    const float* bb    = (const float*)d_in[5];
    const float* wc    = (const float*)d_in[6];
    const float* bc    = (const float*)d_in[7];
    const float* wd    = (const float*)d_in[8];
    const float* bd    = (const float*)d_in[9];
    float* out = (float*)d_out;

    const int smem_bytes = SMEM_FLOATS * sizeof(float);
    cudaFuncSetAttribute(attn_kernel, cudaFuncAttributeMaxDynamicSharedMemorySize, smem_bytes);

    attn_kernel<<<dim3(NPIX / 128, BATCH), 512, smem_bytes>>>(
        fm, depth, wa, ba, wb, bb, wc, bc, wd, bd, out);
}

// round 13
// speedup vs baseline: 1.0964x; 1.0964x over previous
#include <cuda_runtime.h>
#include <math.h>
#include <stdint.h>

#define BATCH 2
#define CH    64
#define CK    8
#define NPIX  9216   // 96*96
#define NB    256    // depth bins
#define BPB   16     // bins per binkv block
#define DLO   (-6.0f)
#define DSCALE ((float)NB / 12.0f)
#define LOG2E 1.4426950408889634f

// Scratch (allocation-free rule: __device__ globals). No cross-replay state.
__device__ float g_l2c[BATCH * NB];          // log2(count) or -1e5
__device__ float g_k_hi[BATCH * NB * CK];    // pre-scaled by log2(e)
__device__ float g_k_lo[BATCH * NB * CK];
__device__ float g_v[BATCH * CH * NB];       // TRANSPOSED [b][c][bin], tf32-rounded

__device__ __forceinline__ float to_tf32(float x) {
    float r; asm("cvt.rna.tf32.f32 %0, %1;" : "=f"(r) : "f"(x)); return r;
}
__device__ __forceinline__ float ex2f(float x) {
    float r; asm("ex2.approx.f32 %0, %1;" : "=f"(r) : "f"(x)); return r;
}
__device__ __forceinline__ void mma4(float* d, const float* a, float b0, float b1) {
    asm("mma.sync.aligned.m16n8k8.row.col.f32.tf32.tf32.f32 "
        "{%0,%1,%2,%3},{%4,%5,%6,%7},{%8,%9},{%0,%1,%2,%3};"
        : "+f"(d[0]), "+f"(d[1]), "+f"(d[2]), "+f"(d[3])
        : "r"(__float_as_uint(a[0])), "r"(__float_as_uint(a[1])),
          "r"(__float_as_uint(a[2])), "r"(__float_as_uint(a[3])),
          "r"(__float_as_uint(b0)), "r"(__float_as_uint(b1)));
}

// ---------------------------------------------------------------------------
// Kernel 1: fused histogram + per-bin k/v projection.
// grid = (NB/BPB, BATCH), block = 1024 (9 scan iterations).
// Per-warp privatized (cnt,sum) rows; projection: 1 channel per thread.
// ---------------------------------------------------------------------------
__global__ void __launch_bounds__(1024) binkv_kernel(
        const float* __restrict__ depth,
        const float* __restrict__ wa, const float* __restrict__ ba,
        const float* __restrict__ wc, const float* __restrict__ bc,
        const float* __restrict__ wd, const float* __restrict__ bd) {
    __shared__ int   scnt[32 * BPB];   // [warp][bin]
    __shared__ float ssum[32 * BPB];
    __shared__ float s_mean[BPB];
    __shared__ float s_wa[CH], s_ba[CH], s_bd[CH], s_bc[CK];
    __shared__ float s_wc[CK * CH];
    __shared__ float s_wd[CH * CH];
    __shared__ float s_df[CH * BPB];

    const int t = threadIdx.x;
    const int w = t >> 5;
    const int b = blockIdx.y;
    const int bin0 = blockIdx.x * BPB;

    if (t < 512) { scnt[t] = 0; ssum[t] = 0.0f; }
    if (t < CH) { s_wa[t] = wa[t]; s_ba[t] = ba[t]; s_bd[t] = bd[t]; }
    if (t < CK) s_bc[t] = bc[t];
    if (t < CK * CH) s_wc[t] = wc[t];
    for (int i = t; i < CH * CH; i += 1024) s_wd[i] = wd[i];
    __syncthreads();

    const float* dep = depth + (size_t)b * NPIX;
#pragma unroll
    for (int i = 0; i < NPIX / 1024; i++) {
        const float v = dep[t + i * 1024];
        int bi = (int)((v - DLO) * DSCALE);
        bi = min(max(bi, 0), NB - 1);
        const int local = bi - bin0;
        if ((unsigned)local < BPB) {
            atomicAdd(&scnt[w * BPB + local], 1);
            atomicAdd(&ssum[w * BPB + local], v);
        }
    }
    __syncthreads();

    if (t < BPB) {
        int   c = 0;
        float s = 0.0f;
#pragma unroll
        for (int ww = 0; ww < 32; ww++) { c += scnt[ww * BPB + t]; s += ssum[ww * BPB + t]; }
        s_mean[t] = (c > 0) ? (s / (float)c) : 0.0f;
        g_l2c[b * NB + bin0 + t] = (c > 0) ? log2f((float)c) : -100000.0f;
    }
    __syncthreads();

    const int bin = t & (BPB - 1);
    const int g   = t >> 4;           // 0..63 -> channel
    const float d = s_mean[bin];

    s_df[g * BPB + bin] = fmaxf(fmaf(s_wa[g], d, s_ba[g]), 0.0f);
    __syncthreads();

    if (g < 8) {    // k projection: dim g
        float acc = s_bc[g];
#pragma unroll 8
        for (int c = 0; c < CH; c++)
            acc = fmaf(s_wc[g * CH + c], s_df[c * BPB + bin], acc);
        const float ks = acc * LOG2E;
        const float hi = to_tf32(ks);
        g_k_hi[((size_t)b * NB + bin0 + bin) * CK + g] = hi;
        g_k_lo[((size_t)b * NB + bin0 + bin) * CK + g] = to_tf32(ks - hi);
    }

    // v projection: channel g
    float a0 = s_bd[g];
#pragma unroll 8
    for (int c = 0; c < CH; c++)
        a0 = fmaf(s_wd[g * CH + c], s_df[c * BPB + bin], a0);
    g_v[(size_t)b * CH * NB + (size_t)g * NB + bin0 + bin] = to_tf32(a0);
}

// ---------------------------------------------------------------------------
// Kernel 2: fused qproj + binned attention (R11 structure; Phase-A chain
// split into two independent MMA accumulators + FADD merge).
// ---------------------------------------------------------------------------
#define KPAD  12
#define VPAD  264
#define SL    0
#define SQ    128
#define SL2C  1152
#define SKH   1408
#define SKL   4480
#define SV    7552
#define SWB   24448
#define SBB   24960
#define FMT   24968
#define REDB  1408
#define RPAD  68
#define RSZ   (128 * RPAD)
#define SMEM_FLOATS (REDB + 4 * RSZ)

__global__ void __launch_bounds__(512, 1) attn_kernel(const float* __restrict__ fm,
                                                      const float* __restrict__ wb,
                                                      const float* __restrict__ bb,
                                                      float* __restrict__ out) {
    extern __shared__ float sm[];

    const int t    = threadIdx.x;
    const int lane = t & 31;
    const int gid  = lane >> 2;
    const int tig  = lane & 3;
    const int wid  = t >> 5;
    const int qi   = wid & 3;
    const int kh   = wid >> 2;
    const int b    = blockIdx.y;
    const int n0   = blockIdx.x * 128;

    // ---- prologue ----
    if (t < 128) sm[SL + t] = 0.0f;
    sm[SWB + t] = wb[t];
    if (t < 8)  sm[SBB + t] = bb[t];
    if (t < NB) sm[SL2C + t] = g_l2c[b * NB + t];

    {
        const float4 k4h = ((const float4*)(g_k_hi + (size_t)b * NB * CK))[t];
        const float4 k4l = ((const float4*)(g_k_lo + (size_t)b * NB * CK))[t];
        const int off = (t >> 1) * KPAD + (t & 1) * 4;
        *(float4*)&sm[SKH + off] = k4h;
        *(float4*)&sm[SKL + off] = k4l;
    }
    {
        const float4* vg4 = (const float4*)(g_v + (size_t)b * CH * NB);
#pragma unroll
        for (int j = 0; j < 8; j++) {
            const int i  = t + j * 512;
            const int c  = i >> 6;
            const int b4 = (i & 63) * 4;
            *(float4*)&sm[SV + c * VPAD + b4] = vg4[i];
        }
    }
    {
        const float* fmb = fm + (size_t)b * CH * NPIX + n0;
#pragma unroll
        for (int i = 0; i < 4; i++) {
            const int idx = t + i * 512;
            const int c   = idx >> 5;
            const int r4  = (idx & 31) * 4;
            *(float4*)&sm[FMT + c * 128 + r4] = *(const float4*)&fmb[(size_t)c * NPIX + r4];
        }
    }
    __syncthreads();

    {
        const int r  = t & 127;
        const int jp = t >> 7;
        float a0 = sm[SBB + 2 * jp], a1 = sm[SBB + 2 * jp + 1];
#pragma unroll 8
        for (int c = 0; c < CH; c++) {
            const float fv = sm[FMT + c * 128 + r];
            a0 = fmaf(sm[SWB + (2 * jp) * CH + c], fv, a0);
            a1 = fmaf(sm[SWB + (2 * jp + 1) * CH + c], fv, a1);
        }
        sm[SQ + r * 8 + 2 * jp]     = a0;
        sm[SQ + r * 8 + 2 * jp + 1] = a1;
    }
    __syncthreads();

    float qhi[2][4], qlo[2][4];
#pragma unroll
    for (int sub = 0; sub < 2; sub++) {
        const int qbase = qi * 32 + sub * 16;
        float v0 = sm[SQ + (qbase + gid) * 8 + tig];
        float v1 = sm[SQ + (qbase + gid + 8) * 8 + tig];
        float v2 = sm[SQ + (qbase + gid) * 8 + tig + 4];
        float v3 = sm[SQ + (qbase + gid + 8) * 8 + tig + 4];
        qhi[sub][0] = to_tf32(v0); qlo[sub][0] = to_tf32(v0 - qhi[sub][0]);
        qhi[sub][1] = to_tf32(v1); qlo[sub][1] = to_tf32(v1 - qhi[sub][1]);
        qhi[sub][2] = to_tf32(v2); qlo[sub][2] = to_tf32(v2 - qhi[sub][2]);
        qhi[sub][3] = to_tf32(v3); qlo[sub][3] = to_tf32(v3 - qhi[sub][3]);
    }

    float acc[2][8][4] = {};
    float lpart[2][2]  = {};

#pragma unroll
    for (int mt = 0; mt < NB / 64; mt++) {
#pragma unroll
        for (int mc = 0; mc < 2; mc++) {
            const int row = mt * 64 + kh * 16 + mc * 8;
            const float* krh = &sm[SKH + (row + gid) * KPAD];
            const float* krl = &sm[SKL + (row + gid) * KPAD];
            const float b0h = krh[tig], b1h = krh[tig + 4];
            const float b0l = krl[tig], b1l = krl[tig + 4];
            const float2 lc = *(const float2*)&sm[SL2C + row + 2 * tig];

            float p[2][4];
#pragma unroll
            for (int sub = 0; sub < 2; sub++) {
                // two independent accumulators, merged by FADD (shorter chain)
                float d0[4] = {lc.x, lc.y, lc.x, lc.y};
                float d1[4] = {0.f, 0.f, 0.f, 0.f};
                mma4(d0, qhi[sub], b0h, b1h);
                mma4(d1, qhi[sub], b0l, b1l);
                mma4(d1, qlo[sub], b0h, b1h);
                p[sub][0] = to_tf32(ex2f(d0[0] + d1[0]));
                p[sub][1] = to_tf32(ex2f(d0[1] + d1[1]));
                p[sub][2] = to_tf32(ex2f(d0[2] + d1[2]));
                p[sub][3] = to_tf32(ex2f(d0[3] + d1[3]));
                lpart[sub][0] += p[sub][0] + p[sub][1];
                lpart[sub][1] += p[sub][2] + p[sub][3];
            }
            const float a0[4] = {p[0][0], p[0][2], p[0][1], p[0][3]};
            const float a1[4] = {p[1][0], p[1][2], p[1][1], p[1][3]};
#pragma unroll
            for (int nc = 0; nc < 8; nc++) {
                const float2 bv = *(const float2*)&sm[SV + (nc * 8 + gid) * VPAD + row + 2 * tig];
                mma4(acc[0][nc], a0, bv.x, bv.y);
                mma4(acc[1][nc], a1, bv.x, bv.y);
            }
        }
    }

#pragma unroll
    for (int sub = 0; sub < 2; sub++)
#pragma unroll
        for (int h = 0; h < 2; h++) {
            float v = lpart[sub][h];
            v += __shfl_xor_sync(0xffffffff, v, 1);
            v += __shfl_xor_sync(0xffffffff, v, 2);
            if (tig == 0) atomicAdd(&sm[SL + qi * 32 + sub * 16 + gid + h * 8], v);
        }
    __syncthreads();

    {
        float* reg = sm + REDB + kh * RSZ;
#pragma unroll
        for (int sub = 0; sub < 2; sub++) {
            const int qrow = qi * 32 + sub * 16 + gid;
#pragma unroll
            for (int nc = 0; nc < 8; nc++) {
                const int c = nc * 8 + 2 * tig;
                *(float2*)&reg[qrow * RPAD + c]       = make_float2(acc[sub][nc][0], acc[sub][nc][1]);
                *(float2*)&reg[(qrow + 8) * RPAD + c] = make_float2(acc[sub][nc][2], acc[sub][nc][3]);
            }
        }
    }
    __syncthreads();

    {
        const int q  = t & 127;
        const int cq = t >> 7;
        const float rl = 1.0f / sm[SL + q];
        const int base = q * RPAD + cq * 16;
        float* ob = out + ((size_t)b * CH + cq * 16) * NPIX + n0 + q;
#pragma unroll
        for (int j = 0; j < 4; j++) {
            float4 s0 = *(float4*)&sm[REDB + 0 * RSZ + base + j * 4];
            float4 s1 = *(float4*)&sm[REDB + 1 * RSZ + base + j * 4];
            float4 s2 = *(float4*)&sm[REDB + 2 * RSZ + base + j * 4];
            float4 s3 = *(float4*)&sm[REDB + 3 * RSZ + base + j * 4];
            ob[(size_t)(j * 4 + 0) * NPIX] = (s0.x + s1.x + s2.x + s3.x) * rl;
            ob[(size_t)(j * 4 + 1) * NPIX] = (s0.y + s1.y + s2.y + s3.y) * rl;
            ob[(size_t)(j * 4 + 2) * NPIX] = (s0.z + s1.z + s2.z + s3.z) * rl;
            ob[(size_t)(j * 4 + 3) * NPIX] = (s0.w + s1.w + s2.w + s3.w) * rl;
        }
    }
}

// ---------------------------------------------------------------------------
extern "C" void kernel_launch(void* const* d_in, const int* in_sizes, int n_in,
                              void* d_out, int out_size) {
    const float* fm    = (const float*)d_in[0];
    const float* depth = (const float*)d_in[1];
    const float* wa    = (const float*)d_in[2];
    const float* ba    = (const float*)d_in[3];
    const float* wb    = (const float*)d_in[4];
    const float* bb    = (const float*)d_in[5];
    const float* wc    = (const float*)d_in[6];
    const float* bc    = (const float*)d_in[7];
    const float* wd    = (const float*)d_in[8];
    const float* bd    = (const float*)d_in[9];
    float* out = (float*)d_out;

    const int smem_bytes = SMEM_FLOATS * sizeof(float);
    cudaFuncSetAttribute(attn_kernel, cudaFuncAttributeMaxDynamicSharedMemorySize, smem_bytes);

    binkv_kernel<<<dim3(NB / BPB, BATCH), 1024>>>(depth, wa, ba, wc, bc, wd, bd);
    attn_kernel<<<dim3(NPIX / 128, BATCH), 512, smem_bytes>>>(fm, wb, bb, out);
}

// round 14
// speedup vs baseline: 1.1098x; 1.0122x over previous
#include <cuda_runtime.h>
#include <math.h>
#include <stdint.h>

#define BATCH 2
#define CH    64
#define CK    8
#define NPIX  9216   // 96*96
#define NB    256    // depth bins
#define BPB   16     // bins per binkv block
#define DLO   (-6.0f)
#define DSCALE ((float)NB / 12.0f)
#define LOG2E 1.4426950408889634f

// Scratch (allocation-free rule: __device__ globals). No cross-replay state.
__device__ float g_l2c[BATCH * NB];          // log2(count) or -1e5
__device__ float g_k_hi[BATCH * NB * CK];    // pre-scaled by log2(e)
__device__ float g_k_lo[BATCH * NB * CK];
__device__ float g_v[BATCH * CH * NB];       // TRANSPOSED [b][c][bin], tf32-rounded

__device__ __forceinline__ float to_tf32(float x) {
    float r; asm("cvt.rna.tf32.f32 %0, %1;" : "=f"(r) : "f"(x)); return r;
}
__device__ __forceinline__ float ex2f(float x) {
    float r; asm("ex2.approx.f32 %0, %1;" : "=f"(r) : "f"(x)); return r;
}
__device__ __forceinline__ void mma4(float* d, const float* a, float b0, float b1) {
    asm("mma.sync.aligned.m16n8k8.row.col.f32.tf32.tf32.f32 "
        "{%0,%1,%2,%3},{%4,%5,%6,%7},{%8,%9},{%0,%1,%2,%3};"
        : "+f"(d[0]), "+f"(d[1]), "+f"(d[2]), "+f"(d[3])
        : "r"(__float_as_uint(a[0])), "r"(__float_as_uint(a[1])),
          "r"(__float_as_uint(a[2])), "r"(__float_as_uint(a[3])),
          "r"(__float_as_uint(b0)), "r"(__float_as_uint(b1)));
}

// Shared smem budget for BOTH kernels (uniform SM carveout across the graph)
#define RPAD  68
#define RSZ   (128 * RPAD)
#define REDB  1408
#define SMEM_FLOATS (REDB + 4 * RSZ)   // 36224 floats = 144896 B

// ---------------------------------------------------------------------------
// Kernel 1: fused histogram + per-bin k/v projection (R11 logic, but scratch
// lives in the SAME-SIZED dynamic smem pool as attn_kernel -> no SM smem
// reconfiguration between the two launches).
// grid = (NB/BPB, BATCH), block = 512. Per-warp privatized (cnt,sum) rows.
// ---------------------------------------------------------------------------
// offsets into dynamic smem (floats)
#define BCNT  0        // 256 ints
#define BSUM  256      // 256
#define BMEAN 512      // 16
#define BWA   528      // 64
#define BBA   592      // 64
#define BBD   656      // 64
#define BBC   720      // 8
#define BWC   728      // 512
#define BWD   1240     // 4096
#define BDF   5336     // 64 x 16

__global__ void __launch_bounds__(512) binkv_kernel(
        const float* __restrict__ depth,
        const float* __restrict__ wa, const float* __restrict__ ba,
        const float* __restrict__ wc, const float* __restrict__ bc,
        const float* __restrict__ wd, const float* __restrict__ bd) {
    extern __shared__ float sb[];
    int* scnt = (int*)&sb[BCNT];

    const int t = threadIdx.x;
    const int w = t >> 5;
    const int b = blockIdx.y;
    const int bin0 = blockIdx.x * BPB;

    if (t < 256) { scnt[t] = 0; sb[BSUM + t] = 0.0f; }
    if (t < CH) { sb[BWA + t] = wa[t]; sb[BBA + t] = ba[t]; sb[BBD + t] = bd[t]; }
    if (t < CK) sb[BBC + t] = bc[t];
    if (t < CK * CH) sb[BWC + t] = wc[t];
    for (int i = t; i < CH * CH; i += 512) sb[BWD + i] = wd[i];
    __syncthreads();

    const float* dep = depth + (size_t)b * NPIX;
#pragma unroll
    for (int i = 0; i < NPIX / 512; i++) {
        const float v = dep[t + i * 512];
        int bi = (int)((v - DLO) * DSCALE);
        bi = min(max(bi, 0), NB - 1);
        const int local = bi - bin0;
        if ((unsigned)local < BPB) {
            atomicAdd(&scnt[w * BPB + local], 1);
            atomicAdd(&sb[BSUM + w * BPB + local], v);
        }
    }
    __syncthreads();

    if (t < BPB) {
        int   c = 0;
        float s = 0.0f;
#pragma unroll
        for (int ww = 0; ww < 16; ww++) { c += scnt[ww * BPB + t]; s += sb[BSUM + ww * BPB + t]; }
        sb[BMEAN + t] = (c > 0) ? (s / (float)c) : 0.0f;
        g_l2c[b * NB + bin0 + t] = (c > 0) ? log2f((float)c) : -100000.0f;
    }
    __syncthreads();

    const int bin = t & (BPB - 1);
    const int g   = t >> 4;           // 0..31
    const float d = sb[BMEAN + bin];

#pragma unroll
    for (int cc = 0; cc < 2; cc++) {
        const int c = g * 2 + cc;
        sb[BDF + c * BPB + bin] = fmaxf(fmaf(sb[BWA + c], d, sb[BBA + c]), 0.0f);
    }
    __syncthreads();

    if (g < 8) {
        float acc = sb[BBC + g];
#pragma unroll 8
        for (int c = 0; c < CH; c++)
            acc = fmaf(sb[BWC + g * CH + c], sb[BDF + c * BPB + bin], acc);
        const float ks = acc * LOG2E;
        const float hi = to_tf32(ks);
        g_k_hi[((size_t)b * NB + bin0 + bin) * CK + g] = hi;
        g_k_lo[((size_t)b * NB + bin0 + bin) * CK + g] = to_tf32(ks - hi);
    }

    float a0 = sb[BBD + g * 2], a1 = sb[BBD + g * 2 + 1];
#pragma unroll 8
    for (int c = 0; c < CH; c++) {
        const float f = sb[BDF + c * BPB + bin];
        a0 = fmaf(sb[BWD + (g * 2) * CH + c], f, a0);
        a1 = fmaf(sb[BWD + (g * 2 + 1) * CH + c], f, a1);
    }
    float* vo = g_v + (size_t)b * CH * NB + bin0 + bin;
    vo[(size_t)(g * 2) * NB]     = to_tf32(a0);
    vo[(size_t)(g * 2 + 1) * NB] = to_tf32(a1);
}

// ---------------------------------------------------------------------------
// Kernel 2: fused qproj + binned attention (byte-identical to R11 best).
// ---------------------------------------------------------------------------
#define KPAD  12
#define VPAD  264
#define SL    0
#define SQ    128
#define SL2C  1152
#define SKH   1408
#define SKL   4480
#define SV    7552
#define SWB   24448
#define SBB   24960
#define FMT   24968

__global__ void __launch_bounds__(512, 1) attn_kernel(const float* __restrict__ fm,
                                                      const float* __restrict__ wb,
                                                      const float* __restrict__ bb,
                                                      float* __restrict__ out) {
    extern __shared__ float sm[];

    const int t    = threadIdx.x;
    const int lane = t & 31;
    const int gid  = lane >> 2;
    const int tig  = lane & 3;
    const int wid  = t >> 5;
    const int qi   = wid & 3;
    const int kh   = wid >> 2;
    const int b    = blockIdx.y;
    const int n0   = blockIdx.x * 128;

    // ---- prologue ----
    if (t < 128) sm[SL + t] = 0.0f;
    sm[SWB + t] = wb[t];
    if (t < 8)  sm[SBB + t] = bb[t];
    if (t < NB) sm[SL2C + t] = g_l2c[b * NB + t];

    {
        const float4 k4h = ((const float4*)(g_k_hi + (size_t)b * NB * CK))[t];
        const float4 k4l = ((const float4*)(g_k_lo + (size_t)b * NB * CK))[t];
        const int off = (t >> 1) * KPAD + (t & 1) * 4;
        *(float4*)&sm[SKH + off] = k4h;
        *(float4*)&sm[SKL + off] = k4l;
    }
    {
        const float4* vg4 = (const float4*)(g_v + (size_t)b * CH * NB);
#pragma unroll
        for (int j = 0; j < 8; j++) {
            const int i  = t + j * 512;
            const int c  = i >> 6;
            const int b4 = (i & 63) * 4;
            *(float4*)&sm[SV + c * VPAD + b4] = vg4[i];
        }
    }
    {
        const float* fmb = fm + (size_t)b * CH * NPIX + n0;
#pragma unroll
        for (int i = 0; i < 4; i++) {
            const int idx = t + i * 512;
            const int c   = idx >> 5;
            const int r4  = (idx & 31) * 4;
            *(float4*)&sm[FMT + c * 128 + r4] = *(const float4*)&fmb[(size_t)c * NPIX + r4];
        }
    }
    __syncthreads();

    {
        const int r  = t & 127;
        const int jp = t >> 7;
        float a0 = sm[SBB + 2 * jp], a1 = sm[SBB + 2 * jp + 1];
#pragma unroll 8
        for (int c = 0; c < CH; c++) {
            const float fv = sm[FMT + c * 128 + r];
            a0 = fmaf(sm[SWB + (2 * jp) * CH + c], fv, a0);
            a1 = fmaf(sm[SWB + (2 * jp + 1) * CH + c], fv, a1);
        }
        sm[SQ + r * 8 + 2 * jp]     = a0;
        sm[SQ + r * 8 + 2 * jp + 1] = a1;
    }
    __syncthreads();

    float qhi[2][4], qlo[2][4];
#pragma unroll
    for (int sub = 0; sub < 2; sub++) {
        const int qbase = qi * 32 + sub * 16;
        float v0 = sm[SQ + (qbase + gid) * 8 + tig];
        float v1 = sm[SQ + (qbase + gid + 8) * 8 + tig];
        float v2 = sm[SQ + (qbase + gid) * 8 + tig + 4];
        float v3 = sm[SQ + (qbase + gid + 8) * 8 + tig + 4];
        qhi[sub][0] = to_tf32(v0); qlo[sub][0] = to_tf32(v0 - qhi[sub][0]);
        qhi[sub][1] = to_tf32(v1); qlo[sub][1] = to_tf32(v1 - qhi[sub][1]);
        qhi[sub][2] = to_tf32(v2); qlo[sub][2] = to_tf32(v2 - qhi[sub][2]);
        qhi[sub][3] = to_tf32(v3); qlo[sub][3] = to_tf32(v3 - qhi[sub][3]);
    }

    float acc[2][8][4] = {};
    float lpart[2][2]  = {};

#pragma unroll
    for (int mt = 0; mt < NB / 64; mt++) {
#pragma unroll
        for (int mc = 0; mc < 2; mc++) {
            const int row = mt * 64 + kh * 16 + mc * 8;
            const float* krh = &sm[SKH + (row + gid) * KPAD];
            const float* krl = &sm[SKL + (row + gid) * KPAD];
            const float b0h = krh[tig], b1h = krh[tig + 4];
            const float b0l = krl[tig], b1l = krl[tig + 4];
            const float2 lc = *(const float2*)&sm[SL2C + row + 2 * tig];

            float p[2][4];
#pragma unroll
            for (int sub = 0; sub < 2; sub++) {
                float d[4] = {lc.x, lc.y, lc.x, lc.y};
                mma4(d, qhi[sub], b0h, b1h);
                mma4(d, qhi[sub], b0l, b1l);
                mma4(d, qlo[sub], b0h, b1h);
                p[sub][0] = to_tf32(ex2f(d[0]));
                p[sub][1] = to_tf32(ex2f(d[1]));
                p[sub][2] = to_tf32(ex2f(d[2]));
                p[sub][3] = to_tf32(ex2f(d[3]));
                lpart[sub][0] += p[sub][0] + p[sub][1];
                lpart[sub][1] += p[sub][2] + p[sub][3];
            }
            const float a0[4] = {p[0][0], p[0][2], p[0][1], p[0][3]};
            const float a1[4] = {p[1][0], p[1][2], p[1][1], p[1][3]};
#pragma unroll
            for (int nc = 0; nc < 8; nc++) {
                const float2 bv = *(const float2*)&sm[SV + (nc * 8 + gid) * VPAD + row + 2 * tig];
                mma4(acc[0][nc], a0, bv.x, bv.y);
                mma4(acc[1][nc], a1, bv.x, bv.y);
            }
        }
    }

#pragma unroll
    for (int sub = 0; sub < 2; sub++)
#pragma unroll
        for (int h = 0; h < 2; h++) {
            float v = lpart[sub][h];
            v += __shfl_xor_sync(0xffffffff, v, 1);
            v += __shfl_xor_sync(0xffffffff, v, 2);
            if (tig == 0) atomicAdd(&sm[SL + qi * 32 + sub * 16 + gid + h * 8], v);
        }
    __syncthreads();

    {
        float* reg = sm + REDB + kh * RSZ;
#pragma unroll
        for (int sub = 0; sub < 2; sub++) {
            const int qrow = qi * 32 + sub * 16 + gid;
#pragma unroll
            for (int nc = 0; nc < 8; nc++) {
                const int c = nc * 8 + 2 * tig;
                *(float2*)&reg[qrow * RPAD + c]       = make_float2(acc[sub][nc][0], acc[sub][nc][1]);
                *(float2*)&reg[(qrow + 8) * RPAD + c] = make_float2(acc[sub][nc][2], acc[sub][nc][3]);
            }
        }
    }
    __syncthreads();

    {
        const int q  = t & 127;
        const int cq = t >> 7;
        const float rl = 1.0f / sm[SL + q];
        const int base = q * RPAD + cq * 16;
        float* ob = out + ((size_t)b * CH + cq * 16) * NPIX + n0 + q;
#pragma unroll
        for (int j = 0; j < 4; j++) {
            float4 s0 = *(float4*)&sm[REDB + 0 * RSZ + base + j * 4];
            float4 s1 = *(float4*)&sm[REDB + 1 * RSZ + base + j * 4];
            float4 s2 = *(float4*)&sm[REDB + 2 * RSZ + base + j * 4];
            float4 s3 = *(float4*)&sm[REDB + 3 * RSZ + base + j * 4];
            ob[(size_t)(j * 4 + 0) * NPIX] = (s0.x + s1.x + s2.x + s3.x) * rl;
            ob[(size_t)(j * 4 + 1) * NPIX] = (s0.y + s1.y + s2.y + s3.y) * rl;
            ob[(size_t)(j * 4 + 2) * NPIX] = (s0.z + s1.z + s2.z + s3.z) * rl;
            ob[(size_t)(j * 4 + 3) * NPIX] = (s0.w + s1.w + s2.w + s3.w) * rl;
        }
    }
}

// ---------------------------------------------------------------------------
extern "C" void kernel_launch(void* const* d_in, const int* in_sizes, int n_in,
                              void* d_out, int out_size) {
    const float* fm    = (const float*)d_in[0];
    const float* depth = (const float*)d_in[1];
    const float* wa    = (const float*)d_in[2];
    const float* ba    = (const float*)d_in[3];
    const float* wb    = (const float*)d_in[4];
    const float* bb    = (const float*)d_in[5];
    const float* wc    = (const float*)d_in[6];
    const float* bc    = (const float*)d_in[7];
    const float* wd    = (const float*)d_in[8];
    const float* bd    = (const float*)d_in[9];
    float* out = (float*)d_out;

    const int smem_bytes = SMEM_FLOATS * sizeof(float);
    cudaFuncSetAttribute(attn_kernel,  cudaFuncAttributeMaxDynamicSharedMemorySize, smem_bytes);
    cudaFuncSetAttribute(binkv_kernel, cudaFuncAttributeMaxDynamicSharedMemorySize, smem_bytes);

    binkv_kernel<<<dim3(NB / BPB, BATCH), 512, smem_bytes>>>(depth, wa, ba, wc, bc, wd, bd);
    attn_kernel<<<dim3(NPIX / 128, BATCH), 512, smem_bytes>>>(fm, wb, bb, out);
}